// round 17
// baseline (speedup 1.0000x reference)
#include <cuda_runtime.h>
#include <cuda_fp16.h>
#include <cstdint>
#include <math.h>

// Problem dims (fixed)
#define BB 32
#define TT 2048
#define DK 512
#define HH 512
#define MM (BB*TT)   // 65536

// Scan chunking
#define CH 16
#define CL (TT/CH)   // 128
#define NCHAIN (BB*HH)  // 16384
#define NQUAD (NCHAIN/4) // 4096

// Scratch
__device__ __align__(16) __half g_z16 [(size_t)MM * HH];  // 64 MB
__device__ __align__(16) __half g_ht16[(size_t)MM * HH];  // 64 MB
__device__ float g_invtau[MM];
__device__ __align__(16) float g_cB [CH * NCHAIN];
__device__ __align__(16) float g_cP [CH * NCHAIN];
__device__ __align__(16) float g_hin[CH * NCHAIN];
__device__ __align__(16) __half g_x16[(size_t)MM * DK];   // 64 MB
__device__ __align__(16) __half g_w16[2 * HH * DK];       // Wz then Wh

// ---------------------------------------------------------------------------
// helpers
// ---------------------------------------------------------------------------
__device__ __forceinline__ uint32_t smem_u32(const void* p) {
    uint32_t a;
    asm("{ .reg .u64 t; cvta.to.shared.u64 t, %1; cvt.u32.u64 %0, t; }"
        : "=r"(a) : "l"(p));
    return a;
}
__device__ __forceinline__ uint32_t packh2(float lo, float hi) {
    uint32_t r;
    asm("cvt.rn.f16x2.f32 %0, %1, %2;" : "=r"(r) : "f"(hi), "f"(lo));
    return r;
}
__device__ __forceinline__ void ldsm4(uint32_t (&r)[4], uint32_t addr) {
    asm volatile("ldmatrix.sync.aligned.m8n8.x4.shared.b16 {%0,%1,%2,%3}, [%4];"
        : "=r"(r[0]), "=r"(r[1]), "=r"(r[2]), "=r"(r[3]) : "r"(addr));
}
__device__ __forceinline__ void mma_f16(float (&d)[4], const uint32_t (&a)[4],
                                        uint32_t b0, uint32_t b1) {
    asm volatile(
        "mma.sync.aligned.m16n8k16.row.col.f32.f16.f16.f32 "
        "{%0,%1,%2,%3}, {%4,%5,%6,%7}, {%8,%9}, {%0,%1,%2,%3};"
        : "+f"(d[0]), "+f"(d[1]), "+f"(d[2]), "+f"(d[3])
        : "r"(a[0]), "r"(a[1]), "r"(a[2]), "r"(a[3]), "r"(b0), "r"(b1));
}
__device__ __forceinline__ void cp16(uint32_t saddr, const void* gptr) {
    asm volatile("cp.async.cg.shared.global [%0], [%1], 16;"
                 :: "r"(saddr), "l"(__cvta_generic_to_global(gptr)));
}
#define CP_COMMIT() asm volatile("cp.async.commit_group;" ::: "memory")
#define CP_WAIT2()  asm volatile("cp.async.wait_group 2;" ::: "memory")

// ---------------------------------------------------------------------------
// Kernel 0: fused prep — cvt_x (blocks [0,16384)), cvt_w, tau
// ---------------------------------------------------------------------------
#define PREP_X_BLKS (MM * DK / 8 / 256)        // 16384
#define PREP_W_BLKS (2 * HH * DK / 8 / 256)    // 256
#define PREP_T_BLKS (MM / 256)                 // 256
#define PREP_BLKS (PREP_X_BLKS + PREP_W_BLKS + PREP_T_BLKS)

__global__ void prep_kernel(const float4* __restrict__ X,
                            const float4* __restrict__ Wz,
                            const float4* __restrict__ Wh,
                            const float* __restrict__ motion_mag,
                            const float* __restrict__ mw,
                            const float* __restrict__ mb,
                            const float* __restrict__ alpha)
{
    const int blk = blockIdx.x;
    if (blk < PREP_X_BLKS) {
        const int i = blk * blockDim.x + threadIdx.x;
        float4 a = X[2 * i];
        float4 b = X[2 * i + 1];
        uint4 o;
        o.x = packh2(a.x, a.y); o.y = packh2(a.z, a.w);
        o.z = packh2(b.x, b.y); o.w = packh2(b.z, b.w);
        ((uint4*)g_x16)[i] = o;
    } else if (blk < PREP_X_BLKS + PREP_W_BLKS) {
        const int i = (blk - PREP_X_BLKS) * blockDim.x + threadIdx.x;
        const int half_n = HH * DK / 8;
        const float4* src = (i < half_n) ? Wz : Wh;
        const int j = (i < half_n) ? i : i - half_n;
        float4 a = src[2 * j];
        float4 b = src[2 * j + 1];
        uint4 o;
        o.x = packh2(a.x, a.y); o.y = packh2(a.z, a.w);
        o.z = packh2(b.x, b.y); o.w = packh2(b.z, b.w);
        ((uint4*)g_w16)[i] = o;
    } else {
        const int i = (blk - PREP_X_BLKS - PREP_W_BLKS) * blockDim.x + threadIdx.x;
        float a  = alpha[0];
        float sp = (a > 20.f) ? a : log1pf(expf(a));
        float t  = mw[0] * motion_mag[i] + mb[0];
        float s  = 1.f / (1.f + expf(-t));
        g_invtau[i] = 1.f / (1.f + sp * s);
    }
}

// ---------------------------------------------------------------------------
// Kernel 2: fused fp16 GEMM (R8 geometry, UNCHANGED): BM=128 BN=256 BK=64,
//   512 threads, 4-stage cp.async pipeline, one __syncthreads per chunk.
// ---------------------------------------------------------------------------
#define A_BYTES 16384                 // 128 rows x 128B
#define B_BYTES 32768                 // 256 rows x 128B
#define STAGE_BYTES (A_BYTES + B_BYTES)
#define NST 4
#define GEMM_SMEM (NST * STAGE_BYTES) // 196608
#define NCHUNK 8

__global__ __launch_bounds__(512, 1)
void gemm_fused(const float* __restrict__ bz, const float* __restrict__ bh)
{
    extern __shared__ uint32_t dsm[];
    const uint32_t sb = smem_u32(dsm);

    const int tid  = threadIdx.x;
    const int lane = tid & 31;
    const int wid  = tid >> 5;
    const int warp_m = wid & 1;
    const int warp_n = wid >> 1;

    const bool GATE = (blockIdx.x < 2);
    const __half* W16  = g_w16 + (GATE ? 0 : (size_t)HH * DK);
    const float* bias  = GATE ? bz : bh;
    const int n0 = (blockIdx.x & 1) * 256;
    const int m0 = blockIdx.y * 128;

    const int lrow = tid >> 3;   // 0..63
    const int lc   = tid & 7;    // 16B chunk in 128B row
    const uint32_t asw = (uint32_t)(((lc ^ (lrow & 7)) << 4));

    const __half* Xrow0 = g_x16 + (size_t)(m0 + lrow) * DK + lc * 8;
    const __half* Wrow0 = W16  + (size_t)(n0 + lrow) * DK + lc * 8;

    const int lr15 = lane & 15;
    const int hi   = lane >> 4;
    const int swz  = lane & 7;
    const uint32_t a_rel = (uint32_t)((warp_m * 64 + lr15) * 128);
    const uint32_t b_rel = (uint32_t)(A_BYTES + (warp_n * 32 + lr15) * 128);

    float acc[4][4][4];
    #pragma unroll
    for (int i = 0; i < 4; i++)
        #pragma unroll
        for (int j = 0; j < 4; j++)
            #pragma unroll
            for (int q = 0; q < 4; q++)
                acc[i][j][q] = 0.f;

    auto load_stage = [&](int ch, int s) {
        const uint32_t sA = sb + (uint32_t)s * STAGE_BYTES;
        const uint32_t sB = sA + A_BYTES;
        const int koff = ch * 64;   // fp16 elements
        #pragma unroll
        for (int j = 0; j < 2; j++)
            cp16(sA + (uint32_t)(lrow + 64 * j) * 128 + asw,
                 Xrow0 + (size_t)(64 * j) * DK + koff);
        #pragma unroll
        for (int j = 0; j < 4; j++)
            cp16(sB + (uint32_t)(lrow + 64 * j) * 128 + asw,
                 Wrow0 + (size_t)(64 * j) * DK + koff);
    };

    #pragma unroll
    for (int s = 0; s < 3; s++) { load_stage(s, s); CP_COMMIT(); }

    for (int ch = 0; ch < NCHUNK; ++ch) {
        CP_WAIT2();
        __syncthreads();

        if (ch + 3 < NCHUNK) load_stage(ch + 3, (ch + 3) & 3);
        CP_COMMIT();

        const uint32_t sbase = sb + (uint32_t)(ch & 3) * STAGE_BYTES;
        const uint32_t a_base = sbase + a_rel;
        const uint32_t b_base = sbase + b_rel;

        #pragma unroll
        for (int ks = 0; ks < 4; ks++) {
            const uint32_t xoff = (uint32_t)(((ks * 2 + hi) ^ swz) << 4);
            uint32_t af[4][4], bf[2][4];
            #pragma unroll
            for (int mt = 0; mt < 4; mt++)
                ldsm4(af[mt], a_base + mt * 2048 + xoff);
            #pragma unroll
            for (int p = 0; p < 2; p++)
                ldsm4(bf[p], b_base + p * 2048 + xoff);
            #pragma unroll
            for (int mt = 0; mt < 4; mt++) {
                #pragma unroll
                for (int p = 0; p < 2; p++) {
                    mma_f16(acc[mt][2*p+0], af[mt], bf[p][0], bf[p][2]);
                    mma_f16(acc[mt][2*p+1], af[mt], bf[p][1], bf[p][3]);
                }
            }
        }
    }

    // ---- epilogue: fp16 half2 stores ----
    uint32_t* out = (uint32_t*)(GATE ? g_z16 : g_ht16);
    #pragma unroll
    for (int mt = 0; mt < 4; mt++) {
        const int m  = m0 + warp_m * 64 + mt * 16 + (lane >> 2);
        const float it0 = GATE ? g_invtau[m]     : 0.f;
        const float it1 = GATE ? g_invtau[m + 8] : 0.f;
        #pragma unroll
        for (int nt = 0; nt < 4; nt++) {
            const int n = n0 + warp_n * 32 + nt * 8 + (lane & 3) * 2;
            const float bs0 = bias[n];
            const float bs1 = bias[n + 1];
            float v0 = acc[mt][nt][0] + bs0;
            float v1 = acc[mt][nt][1] + bs1;
            float v2 = acc[mt][nt][2] + bs0;
            float v3 = acc[mt][nt][3] + bs1;
            if (GATE) {
                v0 = 1.f / (1.f + expf(-v0 * it0));
                v1 = 1.f / (1.f + expf(-v1 * it0));
                v2 = 1.f / (1.f + expf(-v2 * it1));
                v3 = 1.f / (1.f + expf(-v3 * it1));
            }
            out[((size_t)m * HH + n) >> 1]       = packh2(v0, v1);
            out[((size_t)(m + 8) * HH + n) >> 1] = packh2(v2, v3);
        }
    }
}

// ---------------------------------------------------------------------------
// Kernel 3a: per-chunk local scan (h_in = 0), 4 chains/thread via uint2
// ---------------------------------------------------------------------------
__global__ void scan_p1()
{
    const int idx = blockIdx.x * blockDim.x + threadIdx.x; // 0 .. 15*4096-1
    const int q  = idx & (NQUAD - 1);   // chain quad
    const int c  = idx >> 12;           // 0..14
    const int bh = q * 4;
    const int b  = bh >> 9;
    const int h  = bh & 511;
    size_t p = ((size_t)b * TT + (size_t)c * CL) * HH + h;   // fp16 element idx

    const size_t step = HH;
    float hv0 = 0.f, hv1 = 0.f, hv2 = 0.f, hv3 = 0.f;
    float P0 = 1.f, P1 = 1.f, P2 = 1.f, P3 = 1.f;
    #pragma unroll 1
    for (int t = 0; t < CL; t += 8) {
        uint2 zr[8], ar[8];
        #pragma unroll
        for (int u = 0; u < 8; u++) {
            zr[u] = *(const uint2*)(g_z16  + p + (size_t)u * step);
            ar[u] = *(const uint2*)(g_ht16 + p + (size_t)u * step);
        }
        #pragma unroll
        for (int u = 0; u < 8; u++) {
            float2 zlo = __half22float2(*(const __half2*)&zr[u].x);
            float2 zhi = __half22float2(*(const __half2*)&zr[u].y);
            float2 alo = __half22float2(*(const __half2*)&ar[u].x);
            float2 ahi = __half22float2(*(const __half2*)&ar[u].y);
            hv0 = fmaf(zlo.x, alo.x - hv0, hv0); P0 *= (1.f - zlo.x);
            hv1 = fmaf(zlo.y, alo.y - hv1, hv1); P1 *= (1.f - zlo.y);
            hv2 = fmaf(zhi.x, ahi.x - hv2, hv2); P2 *= (1.f - zhi.x);
            hv3 = fmaf(zhi.y, ahi.y - hv3, hv3); P3 *= (1.f - zhi.y);
        }
        p += (size_t)8 * step;
    }
    *(float4*)(g_cB + (size_t)c * NCHAIN + bh) = make_float4(hv0, hv1, hv2, hv3);
    *(float4*)(g_cP + (size_t)c * NCHAIN + bh) = make_float4(P0,  P1,  P2,  P3);
}

// ---------------------------------------------------------------------------
// Kernel 3b: compose chunk carries
// ---------------------------------------------------------------------------
__global__ void scan_p2()
{
    const int bh = blockIdx.x * blockDim.x + threadIdx.x;
    float cb[CH - 1], cp[CH - 1];
    #pragma unroll
    for (int c = 0; c < CH - 1; c++) {
        cb[c] = g_cB[(size_t)c * NCHAIN + bh];
        cp[c] = g_cP[(size_t)c * NCHAIN + bh];
    }
    float hv = 0.f;
    #pragma unroll
    for (int c = 0; c < CH; c++) {
        g_hin[(size_t)c * NCHAIN + bh] = hv;
        if (c < CH - 1) hv = fmaf(cp[c], hv, cb[c]);
    }
}

// ---------------------------------------------------------------------------
// Kernel 3c: final per-chunk scan, 4 chains/thread, float4 output stores
// ---------------------------------------------------------------------------
__global__ void scan_p3(float* __restrict__ out)
{
    const int idx = blockIdx.x * blockDim.x + threadIdx.x; // 0 .. 16*4096-1
    const int q  = idx & (NQUAD - 1);
    const int c  = idx >> 12;           // 0..15
    const int bh = q * 4;
    const int b  = bh >> 9;
    const int h  = bh & 511;
    const size_t base = ((size_t)b * TT + (size_t)c * CL) * HH + h;
    size_t p = base;

    const size_t step = HH;
    float4 hq = *(const float4*)(g_hin + (size_t)c * NCHAIN + bh);
    float hv0 = hq.x, hv1 = hq.y, hv2 = hq.z, hv3 = hq.w;
    float4* po = (float4*)(out + base);
    #pragma unroll 1
    for (int t = 0; t < CL; t += 8) {
        uint2 zr[8], ar[8];
        #pragma unroll
        for (int u = 0; u < 8; u++) {
            zr[u] = *(const uint2*)(g_z16  + p + (size_t)u * step);
            ar[u] = *(const uint2*)(g_ht16 + p + (size_t)u * step);
        }
        #pragma unroll
        for (int u = 0; u < 8; u++) {
            float2 zlo = __half22float2(*(const __half2*)&zr[u].x);
            float2 zhi = __half22float2(*(const __half2*)&zr[u].y);
            float2 alo = __half22float2(*(const __half2*)&ar[u].x);
            float2 ahi = __half22float2(*(const __half2*)&ar[u].y);
            hv0 = fmaf(zlo.x, alo.x - hv0, hv0);
            hv1 = fmaf(zlo.y, alo.y - hv1, hv1);
            hv2 = fmaf(zhi.x, ahi.x - hv2, hv2);
            hv3 = fmaf(zhi.y, ahi.y - hv3, hv3);
            po[(size_t)u * (step / 4)] = make_float4(hv0, hv1, hv2, hv3);
        }
        p  += (size_t)8 * step;
        po += (size_t)8 * (step / 4);
    }
}

// ---------------------------------------------------------------------------
// Launch
// ---------------------------------------------------------------------------
extern "C" void kernel_launch(void* const* d_in, const int* in_sizes, int n_in,
                              void* d_out, int out_size)
{
    const float* x     = (const float*)d_in[0];
    const float* mmg   = (const float*)d_in[1];
    const float* Wz    = (const float*)d_in[2];
    const float* bz    = (const float*)d_in[3];
    const float* Wh    = (const float*)d_in[4];
    const float* bh    = (const float*)d_in[5];
    const float* mw    = (const float*)d_in[6];
    const float* mb    = (const float*)d_in[7];
    const float* alpha = (const float*)d_in[8];
    float* out         = (float*)d_out;

    cudaFuncSetAttribute(gemm_fused, cudaFuncAttributeMaxDynamicSharedMemorySize,
                         GEMM_SMEM);

    prep_kernel<<<PREP_BLKS, 256>>>((const float4*)x, (const float4*)Wz,
                                    (const float4*)Wh, mmg, mw, mb, alpha);

    dim3 grid(4, MM / 128);
    gemm_fused<<<grid, 512, GEMM_SMEM>>>(bz, bh);

    scan_p1<<<(15 * NQUAD) / 256, 256>>>();
    scan_p2<<<NCHAIN / 256, 256>>>();
    scan_p3<<<(CH * NQUAD) / 256, 256>>>(out);
}